// round 4
// baseline (speedup 1.0000x reference)
#include <cuda_runtime.h>

#define Bb 2
#define Ls 2048
#define Dm 1024
#define Hh 16
#define Dk 64
#define Dv 64
#define BHN (Bb*Hh)

__device__ float g_Q[(size_t)Bb*Hh*Ls*Dk];
__device__ float g_K[(size_t)Bb*Hh*Ls*Dk];
__device__ float g_V[(size_t)Bb*Hh*Ls*Dv];
__device__ float g_Z[(size_t)Bb*Ls*Hh*Dv];   // (B, L, H*Dv) head-concat

// ---- tf32 helpers ---------------------------------------------------------
__device__ __forceinline__ unsigned f2tf(float x){
    unsigned r; asm("cvt.rna.tf32.f32 %0, %1;" : "=r"(r) : "f"(x)); return r;
}
__device__ __forceinline__ float f2tff(float x){ return __uint_as_float(f2tf(x)); }

__device__ __forceinline__ void mma8(float c[4], const unsigned a[4], const unsigned b[2]){
    asm volatile("mma.sync.aligned.m16n8k8.row.col.f32.tf32.tf32.f32 "
        "{%0,%1,%2,%3},{%4,%5,%6,%7},{%8,%9},{%0,%1,%2,%3};"
        : "+f"(c[0]),"+f"(c[1]),"+f"(c[2]),"+f"(c[3])
        : "r"(a[0]),"r"(a[1]),"r"(a[2]),"r"(a[3]),"r"(b[0]),"r"(b[1]));
}

__device__ __forceinline__ void cpa16(float* smem_dst, const float* gsrc){
    unsigned s = (unsigned)__cvta_generic_to_shared(smem_dst);
    asm volatile("cp.async.cg.shared.global [%0], [%1], 16;" :: "r"(s), "l"(gsrc));
}
__device__ __forceinline__ void cpa_commit(){ asm volatile("cp.async.commit_group;"); }

// ---------------------------------------------------------------------------
// Kernel 1: QKV projections, double-buffered dynamic smem + register prefetch.
// CTA 128m x 64n, BK=32, 8 warps each 32x32 via m16n8k8 tf32.
// smem layout: sa[2][128][SAP] then sb[2][32][SBP]
// ---------------------------------------------------------------------------
#define SAP 36
#define SBP 72
#define QKV_SA (128 * SAP)
#define QKV_SB (32 * SBP)
#define QKV_SMEM ((2 * QKV_SA + 2 * QKV_SB) * (int)sizeof(float))

__global__ __launch_bounds__(256) void qkv_kernel(
    const float* __restrict__ X,
    const float* __restrict__ Wq, const float* __restrict__ bq,
    const float* __restrict__ Wk, const float* __restrict__ bk,
    const float* __restrict__ Wv, const float* __restrict__ bv)
{
    extern __shared__ float smq[];
    float* sa[2]; sa[0] = smq;              sa[1] = smq + QKV_SA;
    float* sb[2]; sb[0] = smq + 2 * QKV_SA; sb[1] = sb[0] + QKV_SB;

    int z   = blockIdx.y;
    int sel = z / BHN;
    int bh  = z - sel * BHN;
    int b   = bh / Hh;
    int h   = bh - b * Hh;

    const float* W; const float* bias; float* out;
    if (sel == 0)      { W = Wq; bias = bq; out = g_Q; }
    else if (sel == 1) { W = Wk; bias = bk; out = g_K; }
    else               { W = Wv; bias = bv; out = g_V; }
    W    += (size_t)h * Dm * Dk;
    bias += h * Dk;
    out  += (size_t)bh * Ls * Dk + (size_t)blockIdx.x * 128 * Dk;
    const float* A = X + (size_t)b * Ls * Dm + (size_t)blockIdx.x * 128 * Dm;

    int tid = threadIdx.x, lane = tid & 31, warp = tid >> 5;
    int qr = lane >> 2, qc = lane & 3;
    int m0 = (warp & 3) * 32, n0 = (warp >> 2) * 32;

    // prologue: stage kt=0 into buffer 0
    {
#pragma unroll
        for (int i = 0; i < 4; i++) {
            int id = tid + 256 * i; int r = id >> 3, c4 = id & 7;
            float4 v = *(const float4*)(A + (size_t)r * Dm + c4 * 4);
            float4 w; w.x=f2tff(v.x); w.y=f2tff(v.y); w.z=f2tff(v.z); w.w=f2tff(v.w);
            *(float4*)&sa[0][r * SAP + c4 * 4] = w;
        }
#pragma unroll
        for (int i = 0; i < 2; i++) {
            int id = tid + 256 * i; int r = id >> 4, c4 = id & 15;
            float4 v = *(const float4*)(W + (size_t)r * Dk + c4 * 4);
            float4 w; w.x=f2tff(v.x); w.y=f2tff(v.y); w.z=f2tff(v.z); w.w=f2tff(v.w);
            *(float4*)&sb[0][r * SBP + c4 * 4] = w;
        }
    }

    float c[2][4][4] = {};
    float4 ra[4], rb[2];

    for (int kt = 0; kt < 32; ++kt) {
        __syncthreads();
        int cur = kt & 1;
        const float* sac = sa[cur];
        const float* sbc = sb[cur];
        if (kt + 1 < 32) {
#pragma unroll
            for (int i = 0; i < 4; i++) {
                int id = tid + 256 * i; int r = id >> 3, c4 = id & 7;
                ra[i] = *(const float4*)(A + (size_t)r * Dm + (kt + 1) * 32 + c4 * 4);
            }
#pragma unroll
            for (int i = 0; i < 2; i++) {
                int id = tid + 256 * i; int r = id >> 4, c4 = id & 15;
                rb[i] = *(const float4*)(W + (size_t)((kt + 1) * 32 + r) * Dk + c4 * 4);
            }
        }
#pragma unroll
        for (int ks = 0; ks < 4; ++ks) {
            unsigned a[2][4];
#pragma unroll
            for (int mi = 0; mi < 2; mi++) {
                a[mi][0] = __float_as_uint(sac[(m0 + mi * 16 + qr    ) * SAP + ks * 8 + qc    ]);
                a[mi][1] = __float_as_uint(sac[(m0 + mi * 16 + qr + 8) * SAP + ks * 8 + qc    ]);
                a[mi][2] = __float_as_uint(sac[(m0 + mi * 16 + qr    ) * SAP + ks * 8 + qc + 4]);
                a[mi][3] = __float_as_uint(sac[(m0 + mi * 16 + qr + 8) * SAP + ks * 8 + qc + 4]);
            }
#pragma unroll
            for (int nf = 0; nf < 4; nf++) {
                unsigned bb[2];
                bb[0] = __float_as_uint(sbc[(ks * 8 + qc    ) * SBP + n0 + nf * 8 + qr]);
                bb[1] = __float_as_uint(sbc[(ks * 8 + qc + 4) * SBP + n0 + nf * 8 + qr]);
                mma8(c[0][nf], a[0], bb);
                mma8(c[1][nf], a[1], bb);
            }
        }
        if (kt + 1 < 32) {
            int nxt = cur ^ 1;
#pragma unroll
            for (int i = 0; i < 4; i++) {
                int id = tid + 256 * i; int r = id >> 3, c4 = id & 7;
                float4 w; w.x=f2tff(ra[i].x); w.y=f2tff(ra[i].y); w.z=f2tff(ra[i].z); w.w=f2tff(ra[i].w);
                *(float4*)&sa[nxt][r * SAP + c4 * 4] = w;
            }
#pragma unroll
            for (int i = 0; i < 2; i++) {
                int id = tid + 256 * i; int r = id >> 4, c4 = id & 15;
                float4 w; w.x=f2tff(rb[i].x); w.y=f2tff(rb[i].y); w.z=f2tff(rb[i].z); w.w=f2tff(rb[i].w);
                *(float4*)&sb[nxt][r * SBP + c4 * 4] = w;
            }
        }
    }

#pragma unroll
    for (int mi = 0; mi < 2; mi++) {
#pragma unroll
        for (int nf = 0; nf < 4; nf++) {
            int col = n0 + nf * 8 + 2 * qc;
            float bx = bias[col], by = bias[col + 1];
            int row = m0 + mi * 16 + qr;
            *(float2*)(out + (size_t)row * Dk + col)       = make_float2(c[mi][nf][0] + bx, c[mi][nf][1] + by);
            *(float2*)(out + (size_t)(row + 8) * Dk + col) = make_float2(c[mi][nf][2] + bx, c[mi][nf][3] + by);
        }
    }
}

// ---------------------------------------------------------------------------
// Kernel 2: flash attention. Q fragments in registers; K and V double-buffered
// in smem via cp.async (3-group pipeline), in-place tf32 rounding pass per tile.
// ---------------------------------------------------------------------------
#define QSP 68
#define VSP 72
#define FLASH_SMEM ((2 * 128 * QSP + 2 * 128 * VSP) * (int)sizeof(float))

__global__ __launch_bounds__(256) void flash_kernel()
{
    extern __shared__ float sm[];
    float* kb[2]; kb[0] = sm; kb[1] = sm + 128 * QSP;
    float* vb[2]; vb[0] = kb[1] + 128 * QSP; vb[1] = vb[0] + 128 * VSP;

    int bh = blockIdx.y;
    int q0 = blockIdx.x * 128;
    const float* Qg = g_Q + (size_t)bh * Ls * Dk + (size_t)q0 * Dk;
    const float* Kg = g_K + (size_t)bh * Ls * Dk;
    const float* Vg = g_V + (size_t)bh * Ls * Dv;
    int b = bh >> 4, h = bh & 15;

    int tid = threadIdx.x, lane = tid & 31, warp = tid >> 5;
    int qr = lane >> 2, qc = lane & 3;
    int m0 = warp * 16;

    // ---- stage Q through kb[0], extract fragments to registers ----
#pragma unroll
    for (int i = 0; i < 8; i++) {
        int id = tid + 256 * i; int r = id >> 4, c4 = id & 15;
        float4 v = *(const float4*)(Qg + (size_t)r * Dk + c4 * 4);
        float4 w; w.x = f2tff(v.x * 0.125f); w.y = f2tff(v.y * 0.125f);
                  w.z = f2tff(v.z * 0.125f); w.w = f2tff(v.w * 0.125f);
        *(float4*)&kb[0][r * QSP + c4 * 4] = w;
    }
    __syncthreads();
    unsigned aq[8][4];
#pragma unroll
    for (int ks = 0; ks < 8; ++ks) {
        aq[ks][0] = __float_as_uint(kb[0][(m0 + qr    ) * QSP + ks * 8 + qc    ]);
        aq[ks][1] = __float_as_uint(kb[0][(m0 + qr + 8) * QSP + ks * 8 + qc    ]);
        aq[ks][2] = __float_as_uint(kb[0][(m0 + qr    ) * QSP + ks * 8 + qc + 4]);
        aq[ks][3] = __float_as_uint(kb[0][(m0 + qr + 8) * QSP + ks * 8 + qc + 4]);
    }
    __syncthreads();

    // ---- prologue cp.async: K0 -> kb0 | V0 -> vb0 | K1 -> kb1 ----
#pragma unroll
    for (int i = 0; i < 8; i++) {
        int id = tid + 256 * i; int r = id >> 4, c4 = id & 15;
        cpa16(&kb[0][r * QSP + c4 * 4], Kg + (size_t)r * Dk + c4 * 4);
    }
    cpa_commit();
#pragma unroll
    for (int i = 0; i < 8; i++) {
        int id = tid + 256 * i; int r = id >> 4, c4 = id & 15;
        cpa16(&vb[0][r * VSP + c4 * 4], Vg + (size_t)r * Dv + c4 * 4);
    }
    cpa_commit();
#pragma unroll
    for (int i = 0; i < 8; i++) {
        int id = tid + 256 * i; int r = id >> 4, c4 = id & 15;
        cpa16(&kb[1][r * QSP + c4 * 4], Kg + (size_t)(128 + r) * Dk + c4 * 4);
    }
    cpa_commit();

    float co[8][4] = {};
    float mA = -1e30f, mB = -1e30f, lA = 0.f, lB = 0.f;

    int base = lane & ~3;
    int s0 = base + (qc >> 1), s1 = s0 + 2;
    bool odd = (qc & 1);

    for (int t = 0; t < Ls / 128; ++t) {
        float* kcur = kb[t & 1];
        float* vcur = vb[t & 1];
        float* vnxt = vb[(t + 1) & 1];

        asm volatile("cp.async.wait_group 2;");   // K(t) landed
        __syncthreads();

        // in-place tf32 rounding on K tile
#pragma unroll
        for (int i = 0; i < 8; i++) {
            int id = tid + 256 * i; int r = id >> 4, c4 = id & 15;
            float4 v = *(float4*)&kcur[r * QSP + c4 * 4];
            v.x = f2tff(v.x); v.y = f2tff(v.y); v.z = f2tff(v.z); v.w = f2tff(v.w);
            *(float4*)&kcur[r * QSP + c4 * 4] = v;
        }
        __syncthreads();

        // ---- S = Q K^T : per warp 16 x 128 in registers ----
        float sc[16][4] = {};
#pragma unroll
        for (int ks = 0; ks < 8; ++ks) {
#pragma unroll
            for (int nf = 0; nf < 16; nf++) {
                unsigned bb[2];
                bb[0] = __float_as_uint(kcur[(nf * 8 + qr) * QSP + ks * 8 + qc    ]);
                bb[1] = __float_as_uint(kcur[(nf * 8 + qr) * QSP + ks * 8 + qc + 4]);
                mma8(sc[nf], aq[ks], bb);
            }
        }

        // ---- online softmax in registers ----
        float mxA = -1e30f, mxB = -1e30f;
#pragma unroll
        for (int nf = 0; nf < 16; nf++) {
            mxA = fmaxf(mxA, fmaxf(sc[nf][0], sc[nf][1]));
            mxB = fmaxf(mxB, fmaxf(sc[nf][2], sc[nf][3]));
        }
        mxA = fmaxf(mxA, __shfl_xor_sync(0xffffffffu, mxA, 1));
        mxA = fmaxf(mxA, __shfl_xor_sync(0xffffffffu, mxA, 2));
        mxB = fmaxf(mxB, __shfl_xor_sync(0xffffffffu, mxB, 1));
        mxB = fmaxf(mxB, __shfl_xor_sync(0xffffffffu, mxB, 2));

        float mnA = fmaxf(mA, mxA), mnB = fmaxf(mB, mxB);
        float aAl = __expf(mA - mnA), aBl = __expf(mB - mnB);
        float sA = 0.f, sB = 0.f;
#pragma unroll
        for (int nf = 0; nf < 16; nf++) {
            float p0 = __expf(sc[nf][0] - mnA);
            float p1 = __expf(sc[nf][1] - mnA);
            float p2 = __expf(sc[nf][2] - mnB);
            float p3 = __expf(sc[nf][3] - mnB);
            sA += p0 + p1; sB += p2 + p3;
            sc[nf][0] = f2tff(p0); sc[nf][1] = f2tff(p1);
            sc[nf][2] = f2tff(p2); sc[nf][3] = f2tff(p3);
        }
        sA += __shfl_xor_sync(0xffffffffu, sA, 1);
        sA += __shfl_xor_sync(0xffffffffu, sA, 2);
        sB += __shfl_xor_sync(0xffffffffu, sB, 1);
        sB += __shfl_xor_sync(0xffffffffu, sB, 2);
        lA = lA * aAl + sA; mA = mnA;
        lB = lB * aBl + sB; mB = mnB;

#pragma unroll
        for (int vf = 0; vf < 8; vf++) {
            co[vf][0] *= aAl; co[vf][1] *= aAl;
            co[vf][2] *= aBl; co[vf][3] *= aBl;
        }

        asm volatile("cp.async.wait_group 1;");   // V(t) landed
        __syncthreads();

        // issue next-tile copies (V(t+1) -> vnxt, K(t+2) -> kcur); always commit
        if (t + 1 < Ls / 128) {
#pragma unroll
            for (int i = 0; i < 8; i++) {
                int id = tid + 256 * i; int r = id >> 4, c4 = id & 15;
                cpa16(&vnxt[r * VSP + c4 * 4], Vg + (size_t)((t + 1) * 128 + r) * Dv + c4 * 4);
            }
        }
        cpa_commit();
        if (t + 2 < Ls / 128) {
#pragma unroll
            for (int i = 0; i < 8; i++) {
                int id = tid + 256 * i; int r = id >> 4, c4 = id & 15;
                cpa16(&kcur[r * QSP + c4 * 4], Kg + (size_t)((t + 2) * 128 + r) * Dk + c4 * 4);
            }
        }
        cpa_commit();

        // in-place tf32 rounding on V tile
#pragma unroll
        for (int i = 0; i < 8; i++) {
            int id = tid + 256 * i; int r = id >> 4, c4 = id & 15;
            float4 v = *(float4*)&vcur[r * VSP + c4 * 4];
            v.x = f2tff(v.x); v.y = f2tff(v.y); v.z = f2tff(v.z); v.w = f2tff(v.w);
            *(float4*)&vcur[r * VSP + c4 * 4] = v;
        }
        __syncthreads();

        // ---- O += P V ----
#pragma unroll
        for (int kk = 0; kk < 16; ++kk) {
            float t00 = __shfl_sync(0xffffffffu, sc[kk][0], s0);
            float t01 = __shfl_sync(0xffffffffu, sc[kk][1], s0);
            float t10 = __shfl_sync(0xffffffffu, sc[kk][2], s0);
            float t11 = __shfl_sync(0xffffffffu, sc[kk][3], s0);
            float u00 = __shfl_sync(0xffffffffu, sc[kk][0], s1);
            float u01 = __shfl_sync(0xffffffffu, sc[kk][1], s1);
            float u10 = __shfl_sync(0xffffffffu, sc[kk][2], s1);
            float u11 = __shfl_sync(0xffffffffu, sc[kk][3], s1);
            unsigned a[4];
            a[0] = __float_as_uint(odd ? t01 : t00);
            a[1] = __float_as_uint(odd ? t11 : t10);
            a[2] = __float_as_uint(odd ? u01 : u00);
            a[3] = __float_as_uint(odd ? u11 : u10);
#pragma unroll
            for (int vf = 0; vf < 8; vf++) {
                unsigned bb[2];
                bb[0] = __float_as_uint(vcur[(kk * 8 + qc    ) * VSP + vf * 8 + qr]);
                bb[1] = __float_as_uint(vcur[(kk * 8 + qc + 4) * VSP + vf * 8 + qr]);
                mma8(co[vf], a, bb);
            }
        }
    }

    float iA = 1.0f / lA, iB = 1.0f / lB;
    float* Zg = g_Z + ((size_t)(b * Ls + q0 + m0)) * (Hh * Dv) + h * Dv;
#pragma unroll
    for (int vf = 0; vf < 8; vf++) {
        int col = vf * 8 + 2 * qc;
        *(float2*)(Zg + (size_t)qr * (Hh * Dv) + col)       = make_float2(co[vf][0] * iA, co[vf][1] * iA);
        *(float2*)(Zg + (size_t)(qr + 8) * (Hh * Dv) + col) = make_float2(co[vf][2] * iB, co[vf][3] * iB);
    }
}

// ---------------------------------------------------------------------------
// Kernel 3: output projection, double-buffered dynamic smem like qkv.
// out[m][n] = sum_k Z[m][k]*Wo[n][k] + bo[n], M=4096 N=1024 K=1024.
// smem: sa[2][128][SAP] then swo[2][64][SAP]
// ---------------------------------------------------------------------------
#define OP_SA (128 * SAP)
#define OP_SW (64 * SAP)
#define OP_SMEM ((2 * OP_SA + 2 * OP_SW) * (int)sizeof(float))

__global__ __launch_bounds__(256) void oproj_kernel(
    const float* __restrict__ Wo, const float* __restrict__ bo,
    float* __restrict__ out)
{
    extern __shared__ float smo[];
    float* sa[2];  sa[0] = smo;              sa[1] = smo + OP_SA;
    float* swo[2]; swo[0] = smo + 2 * OP_SA; swo[1] = swo[0] + OP_SW;

    const int N = Dm, K = Hh * Dv;

    const float* A = g_Z + (size_t)blockIdx.x * 128 * K;
    int n0g = blockIdx.y * 64;

    int tid = threadIdx.x, lane = tid & 31, warp = tid >> 5;
    int qr = lane >> 2, qc = lane & 3;
    int m0 = (warp & 3) * 32, n0 = (warp >> 2) * 32;

    {
#pragma unroll
        for (int i = 0; i < 4; i++) {
            int id = tid + 256 * i; int r = id >> 3, c4 = id & 7;
            float4 v = *(const float4*)(A + (size_t)r * K + c4 * 4);
            float4 w; w.x=f2tff(v.x); w.y=f2tff(v.y); w.z=f2tff(v.z); w.w=f2tff(v.w);
            *(float4*)&sa[0][r * SAP + c4 * 4] = w;
        }
#pragma unroll
        for (int i = 0; i < 2; i++) {
            int id = tid + 256 * i; int r = id >> 3, c4 = id & 7;
            float4 v = *(const float4*)(Wo + (size_t)(n0g + r) * K + c4 * 4);
            float4 w; w.x=f2tff(v.x); w.y=f2tff(v.y); w.z=f2tff(v.z); w.w=f2tff(v.w);
            *(float4*)&swo[0][r * SAP + c4 * 4] = w;
        }
    }

    float c[2][4][4] = {};
    float4 ra[4], rb[2];

    for (int kt = 0; kt < K / 32; ++kt) {
        __syncthreads();
        int cur = kt & 1;
        const float* sac = sa[cur];
        const float* swc = swo[cur];
        if (kt + 1 < K / 32) {
#pragma unroll
            for (int i = 0; i < 4; i++) {
                int id = tid + 256 * i; int r = id >> 3, c4 = id & 7;
                ra[i] = *(const float4*)(A + (size_t)r * K + (kt + 1) * 32 + c4 * 4);
            }
#pragma unroll
            for (int i = 0; i < 2; i++) {
                int id = tid + 256 * i; int r = id >> 3, c4 = id & 7;
                rb[i] = *(const float4*)(Wo + (size_t)(n0g + r) * K + (kt + 1) * 32 + c4 * 4);
            }
        }
#pragma unroll
        for (int ks = 0; ks < 4; ++ks) {
            unsigned a[2][4];
#pragma unroll
            for (int mi = 0; mi < 2; mi++) {
                a[mi][0] = __float_as_uint(sac[(m0 + mi * 16 + qr    ) * SAP + ks * 8 + qc    ]);
                a[mi][1] = __float_as_uint(sac[(m0 + mi * 16 + qr + 8) * SAP + ks * 8 + qc    ]);
                a[mi][2] = __float_as_uint(sac[(m0 + mi * 16 + qr    ) * SAP + ks * 8 + qc + 4]);
                a[mi][3] = __float_as_uint(sac[(m0 + mi * 16 + qr + 8) * SAP + ks * 8 + qc + 4]);
            }
#pragma unroll
            for (int nf = 0; nf < 4; nf++) {
                unsigned bb[2];
                bb[0] = __float_as_uint(swc[(n0 + nf * 8 + qr) * SAP + ks * 8 + qc    ]);
                bb[1] = __float_as_uint(swc[(n0 + nf * 8 + qr) * SAP + ks * 8 + qc + 4]);
                mma8(c[0][nf], a[0], bb);
                mma8(c[1][nf], a[1], bb);
            }
        }
        if (kt + 1 < K / 32) {
            int nxt = cur ^ 1;
#pragma unroll
            for (int i = 0; i < 4; i++) {
                int id = tid + 256 * i; int r = id >> 3, c4 = id & 7;
                float4 w; w.x=f2tff(ra[i].x); w.y=f2tff(ra[i].y); w.z=f2tff(ra[i].z); w.w=f2tff(ra[i].w);
                *(float4*)&sa[nxt][r * SAP + c4 * 4] = w;
            }
#pragma unroll
            for (int i = 0; i < 2; i++) {
                int id = tid + 256 * i; int r = id >> 3, c4 = id & 7;
                float4 w; w.x=f2tff(rb[i].x); w.y=f2tff(rb[i].y); w.z=f2tff(rb[i].z); w.w=f2tff(rb[i].w);
                *(float4*)&swo[nxt][r * SAP + c4 * 4] = w;
            }
        }
    }

#pragma unroll
    for (int mi = 0; mi < 2; mi++) {
#pragma unroll
        for (int nf = 0; nf < 4; nf++) {
            int col = n0g + n0 + nf * 8 + 2 * qc;
            float bx = bo[col], by = bo[col + 1];
            int row = blockIdx.x * 128 + m0 + mi * 16 + qr;
            *(float2*)(out + (size_t)row * N + col)       = make_float2(c[mi][nf][0] + bx, c[mi][nf][1] + by);
            *(float2*)(out + (size_t)(row + 8) * N + col) = make_float2(c[mi][nf][2] + bx, c[mi][nf][3] + by);
        }
    }
}

// ---------------------------------------------------------------------------
extern "C" void kernel_launch(void* const* d_in, const int* in_sizes, int n_in,
                              void* d_out, int out_size)
{
    const float* X  = (const float*)d_in[0];
    const float* Wq = (const float*)d_in[1];
    const float* bq = (const float*)d_in[2];
    const float* Wk = (const float*)d_in[3];
    const float* bk = (const float*)d_in[4];
    const float* Wv = (const float*)d_in[5];
    const float* bv = (const float*)d_in[6];
    const float* Wo = (const float*)d_in[7];
    const float* bo = (const float*)d_in[8];
    float* out = (float*)d_out;

    (void)in_sizes; (void)n_in; (void)out_size;

    cudaFuncSetAttribute(qkv_kernel,   cudaFuncAttributeMaxDynamicSharedMemorySize, QKV_SMEM);
    cudaFuncSetAttribute(flash_kernel, cudaFuncAttributeMaxDynamicSharedMemorySize, FLASH_SMEM);
    cudaFuncSetAttribute(oproj_kernel, cudaFuncAttributeMaxDynamicSharedMemorySize, OP_SMEM);

    qkv_kernel<<<dim3(Ls / 128, 3 * BHN), 256, QKV_SMEM>>>(X, Wq, bq, Wk, bk, Wv, bv);
    flash_kernel<<<dim3(Ls / 128, BHN), 256, FLASH_SMEM>>>();
    oproj_kernel<<<dim3((Bb * Ls) / 128, Dm / 64), 256, OP_SMEM>>>(Wo, bo, out);
}

// round 5
// speedup vs baseline: 1.3986x; 1.3986x over previous
#include <cuda_runtime.h>

#define Bb 2
#define Ls 2048
#define Dm 1024
#define Hh 16
#define Dk 64
#define Dv 64
#define BHN (Bb*Hh)

__device__ float g_Q[(size_t)Bb*Hh*Ls*Dk];
__device__ float g_K[(size_t)Bb*Hh*Ls*Dk];
__device__ float g_V[(size_t)Bb*Hh*Ls*Dv];
__device__ float g_Z[(size_t)Bb*Ls*Hh*Dv];   // (B, L, H*Dv) head-concat

// ---- tf32 helpers ---------------------------------------------------------
__device__ __forceinline__ unsigned f2tf(float x){
    unsigned r; asm("cvt.rna.tf32.f32 %0, %1;" : "=r"(r) : "f"(x)); return r;
}
__device__ __forceinline__ float f2tff(float x){ return __uint_as_float(f2tf(x)); }

__device__ __forceinline__ void mma8(float c[4], const unsigned a[4], const unsigned b[2]){
    asm volatile("mma.sync.aligned.m16n8k8.row.col.f32.tf32.tf32.f32 "
        "{%0,%1,%2,%3},{%4,%5,%6,%7},{%8,%9},{%0,%1,%2,%3};"
        : "+f"(c[0]),"+f"(c[1]),"+f"(c[2]),"+f"(c[3])
        : "r"(a[0]),"r"(a[1]),"r"(a[2]),"r"(a[3]),"r"(b[0]),"r"(b[1]));
}

// ---------------------------------------------------------------------------
// Kernel 1: QKV projections. Static single-buffer smem, register prefetch:
//   store(kt) -> bar -> prefetch(kt+1 into regs, overlaps mma) -> mma -> bar
// CTA 128m x 64n, BK=32, 8 warps each 32x32 via m16n8k8 tf32.
// ---------------------------------------------------------------------------
#define SAP 36
#define SBP 72

__global__ __launch_bounds__(256) void qkv_kernel(
    const float* __restrict__ X,
    const float* __restrict__ Wq, const float* __restrict__ bq,
    const float* __restrict__ Wk, const float* __restrict__ bk,
    const float* __restrict__ Wv, const float* __restrict__ bv)
{
    __shared__ float sa[128][SAP];
    __shared__ float sb[32][SBP];

    int z   = blockIdx.y;
    int sel = z / BHN;
    int bh  = z - sel * BHN;
    int b   = bh / Hh;
    int h   = bh - b * Hh;

    const float* W; const float* bias; float* out;
    if (sel == 0)      { W = Wq; bias = bq; out = g_Q; }
    else if (sel == 1) { W = Wk; bias = bk; out = g_K; }
    else               { W = Wv; bias = bv; out = g_V; }
    W    += (size_t)h * Dm * Dk;
    bias += h * Dk;
    out  += (size_t)bh * Ls * Dk + (size_t)blockIdx.x * 128 * Dk;
    const float* A = X + (size_t)b * Ls * Dm + (size_t)blockIdx.x * 128 * Dm;

    int tid = threadIdx.x, lane = tid & 31, warp = tid >> 5;
    int qr = lane >> 2, qc = lane & 3;
    int m0 = (warp & 3) * 32, n0 = (warp >> 2) * 32;

    float4 ra[4], rb[2];
    // prologue: load kt=0 into regs
#pragma unroll
    for (int i = 0; i < 4; i++) {
        int id = tid + 256 * i; int r = id >> 3, c4 = id & 7;
        ra[i] = *(const float4*)(A + (size_t)r * Dm + c4 * 4);
    }
#pragma unroll
    for (int i = 0; i < 2; i++) {
        int id = tid + 256 * i; int r = id >> 4, c4 = id & 15;
        rb[i] = *(const float4*)(W + (size_t)r * Dk + c4 * 4);
    }

    float c[2][4][4] = {};

    for (int kt = 0; kt < 32; ++kt) {
        // commit staged regs to smem (with tf32 rounding)
#pragma unroll
        for (int i = 0; i < 4; i++) {
            int id = tid + 256 * i; int r = id >> 3, c4 = id & 7;
            float4 w; w.x=f2tff(ra[i].x); w.y=f2tff(ra[i].y); w.z=f2tff(ra[i].z); w.w=f2tff(ra[i].w);
            *(float4*)&sa[r][c4 * 4] = w;
        }
#pragma unroll
        for (int i = 0; i < 2; i++) {
            int id = tid + 256 * i; int r = id >> 4, c4 = id & 15;
            float4 w; w.x=f2tff(rb[i].x); w.y=f2tff(rb[i].y); w.z=f2tff(rb[i].z); w.w=f2tff(rb[i].w);
            *(float4*)&sb[r][c4 * 4] = w;
        }
        __syncthreads();
        // prefetch next tile (global latency overlaps the mma loop below)
        if (kt + 1 < 32) {
#pragma unroll
            for (int i = 0; i < 4; i++) {
                int id = tid + 256 * i; int r = id >> 3, c4 = id & 7;
                ra[i] = *(const float4*)(A + (size_t)r * Dm + (kt + 1) * 32 + c4 * 4);
            }
#pragma unroll
            for (int i = 0; i < 2; i++) {
                int id = tid + 256 * i; int r = id >> 4, c4 = id & 15;
                rb[i] = *(const float4*)(W + (size_t)((kt + 1) * 32 + r) * Dk + c4 * 4);
            }
        }
#pragma unroll
        for (int ks = 0; ks < 4; ++ks) {
            unsigned a[2][4];
#pragma unroll
            for (int mi = 0; mi < 2; mi++) {
                a[mi][0] = __float_as_uint(sa[m0 + mi * 16 + qr    ][ks * 8 + qc    ]);
                a[mi][1] = __float_as_uint(sa[m0 + mi * 16 + qr + 8][ks * 8 + qc    ]);
                a[mi][2] = __float_as_uint(sa[m0 + mi * 16 + qr    ][ks * 8 + qc + 4]);
                a[mi][3] = __float_as_uint(sa[m0 + mi * 16 + qr + 8][ks * 8 + qc + 4]);
            }
#pragma unroll
            for (int nf = 0; nf < 4; nf++) {
                unsigned bb[2];
                bb[0] = __float_as_uint(sb[ks * 8 + qc    ][n0 + nf * 8 + qr]);
                bb[1] = __float_as_uint(sb[ks * 8 + qc + 4][n0 + nf * 8 + qr]);
                mma8(c[0][nf], a[0], bb);
                mma8(c[1][nf], a[1], bb);
            }
        }
        __syncthreads();
    }

#pragma unroll
    for (int mi = 0; mi < 2; mi++) {
#pragma unroll
        for (int nf = 0; nf < 4; nf++) {
            int col = n0 + nf * 8 + 2 * qc;
            float bx = bias[col], by = bias[col + 1];
            int row = m0 + mi * 16 + qr;
            *(float2*)(out + (size_t)row * Dk + col)       = make_float2(c[mi][nf][0] + bx, c[mi][nf][1] + by);
            *(float2*)(out + (size_t)(row + 8) * Dk + col) = make_float2(c[mi][nf][2] + bx, c[mi][nf][3] + by);
        }
    }
}

// ---------------------------------------------------------------------------
// Kernel 2: flash attention (round-2 structure — best measured).
// CTA = 128 q-rows, KV tiles of 128; 8 warps, each 16 q-rows x 128 keys.
// S/P in registers, online softmax via quad shfl, P->A frag via intra-quad shfl.
// ---------------------------------------------------------------------------
#define QSP 68
#define VSP 72
#define FLASH_SMEM ((2 * 128 * QSP + 128 * VSP) * (int)sizeof(float))

__global__ __launch_bounds__(256) void flash_kernel()
{
    extern __shared__ float sm[];
    float* qs  = sm;                   // [128][68]
    float* ksm = qs + 128 * QSP;       // [128][68]
    float* vsm = ksm + 128 * QSP;      // [128][72]

    int bh = blockIdx.y;
    int q0 = blockIdx.x * 128;
    const float* Qg = g_Q + (size_t)bh * Ls * Dk + (size_t)q0 * Dk;
    const float* Kg = g_K + (size_t)bh * Ls * Dk;
    const float* Vg = g_V + (size_t)bh * Ls * Dv;
    int b = bh >> 4, h = bh & 15;

    int tid = threadIdx.x, lane = tid & 31, warp = tid >> 5;
    int qr = lane >> 2, qc = lane & 3;
    int m0 = warp * 16;

    // load Q tile (scale folded, tf32-rounded)
#pragma unroll
    for (int i = 0; i < 8; i++) {
        int id = tid + 256 * i; int r = id >> 4, c4 = id & 15;
        float4 v = *(const float4*)(Qg + (size_t)r * Dk + c4 * 4);
        float4 w; w.x = f2tff(v.x * 0.125f); w.y = f2tff(v.y * 0.125f);
                  w.z = f2tff(v.z * 0.125f); w.w = f2tff(v.w * 0.125f);
        *(float4*)&qs[r * QSP + c4 * 4] = w;
    }

    float co[8][4] = {};
    float mA = -1e30f, mB = -1e30f, lA = 0.f, lB = 0.f;

    int base = lane & ~3;
    int s0 = base + (qc >> 1), s1 = s0 + 2;
    bool odd = (qc & 1);

    for (int t = 0; t < Ls / 128; ++t) {
#pragma unroll
        for (int i = 0; i < 8; i++) {
            int id = tid + 256 * i; int r = id >> 4, c4 = id & 15;
            float4 v = *(const float4*)(Kg + (size_t)(t * 128 + r) * Dk + c4 * 4);
            float4 w; w.x = f2tff(v.x); w.y = f2tff(v.y); w.z = f2tff(v.z); w.w = f2tff(v.w);
            *(float4*)&ksm[r * QSP + c4 * 4] = w;
            float4 u = *(const float4*)(Vg + (size_t)(t * 128 + r) * Dv + c4 * 4);
            float4 x; x.x = f2tff(u.x); x.y = f2tff(u.y); x.z = f2tff(u.z); x.w = f2tff(u.w);
            *(float4*)&vsm[r * VSP + c4 * 4] = x;
        }
        __syncthreads();

        // S = Q K^T
        float sc[16][4] = {};
#pragma unroll
        for (int ks = 0; ks < 8; ++ks) {
            unsigned a[4];
            a[0] = __float_as_uint(qs[(m0 + qr    ) * QSP + ks * 8 + qc    ]);
            a[1] = __float_as_uint(qs[(m0 + qr + 8) * QSP + ks * 8 + qc    ]);
            a[2] = __float_as_uint(qs[(m0 + qr    ) * QSP + ks * 8 + qc + 4]);
            a[3] = __float_as_uint(qs[(m0 + qr + 8) * QSP + ks * 8 + qc + 4]);
#pragma unroll
            for (int nf = 0; nf < 16; nf++) {
                unsigned bb[2];
                bb[0] = __float_as_uint(ksm[(nf * 8 + qr) * QSP + ks * 8 + qc    ]);
                bb[1] = __float_as_uint(ksm[(nf * 8 + qr) * QSP + ks * 8 + qc + 4]);
                mma8(sc[nf], a, bb);
            }
        }

        // online softmax in registers
        float mxA = -1e30f, mxB = -1e30f;
#pragma unroll
        for (int nf = 0; nf < 16; nf++) {
            mxA = fmaxf(mxA, fmaxf(sc[nf][0], sc[nf][1]));
            mxB = fmaxf(mxB, fmaxf(sc[nf][2], sc[nf][3]));
        }
        mxA = fmaxf(mxA, __shfl_xor_sync(0xffffffffu, mxA, 1));
        mxA = fmaxf(mxA, __shfl_xor_sync(0xffffffffu, mxA, 2));
        mxB = fmaxf(mxB, __shfl_xor_sync(0xffffffffu, mxB, 1));
        mxB = fmaxf(mxB, __shfl_xor_sync(0xffffffffu, mxB, 2));

        float mnA = fmaxf(mA, mxA), mnB = fmaxf(mB, mxB);
        float aAl = __expf(mA - mnA), aBl = __expf(mB - mnB);
        float sA = 0.f, sB = 0.f;
#pragma unroll
        for (int nf = 0; nf < 16; nf++) {
            float p0 = __expf(sc[nf][0] - mnA);
            float p1 = __expf(sc[nf][1] - mnA);
            float p2 = __expf(sc[nf][2] - mnB);
            float p3 = __expf(sc[nf][3] - mnB);
            sA += p0 + p1; sB += p2 + p3;
            sc[nf][0] = f2tff(p0); sc[nf][1] = f2tff(p1);
            sc[nf][2] = f2tff(p2); sc[nf][3] = f2tff(p3);
        }
        sA += __shfl_xor_sync(0xffffffffu, sA, 1);
        sA += __shfl_xor_sync(0xffffffffu, sA, 2);
        sB += __shfl_xor_sync(0xffffffffu, sB, 1);
        sB += __shfl_xor_sync(0xffffffffu, sB, 2);
        lA = lA * aAl + sA; mA = mnA;
        lB = lB * aBl + sB; mB = mnB;

#pragma unroll
        for (int vf = 0; vf < 8; vf++) {
            co[vf][0] *= aAl; co[vf][1] *= aAl;
            co[vf][2] *= aBl; co[vf][3] *= aBl;
        }

        // O += P V
#pragma unroll
        for (int kk = 0; kk < 16; ++kk) {
            float t00 = __shfl_sync(0xffffffffu, sc[kk][0], s0);
            float t01 = __shfl_sync(0xffffffffu, sc[kk][1], s0);
            float t10 = __shfl_sync(0xffffffffu, sc[kk][2], s0);
            float t11 = __shfl_sync(0xffffffffu, sc[kk][3], s0);
            float u00 = __shfl_sync(0xffffffffu, sc[kk][0], s1);
            float u01 = __shfl_sync(0xffffffffu, sc[kk][1], s1);
            float u10 = __shfl_sync(0xffffffffu, sc[kk][2], s1);
            float u11 = __shfl_sync(0xffffffffu, sc[kk][3], s1);
            unsigned a[4];
            a[0] = __float_as_uint(odd ? t01 : t00);
            a[1] = __float_as_uint(odd ? t11 : t10);
            a[2] = __float_as_uint(odd ? u01 : u00);
            a[3] = __float_as_uint(odd ? u11 : u10);
#pragma unroll
            for (int vf = 0; vf < 8; vf++) {
                unsigned bb[2];
                bb[0] = __float_as_uint(vsm[(kk * 8 + qc    ) * VSP + vf * 8 + qr]);
                bb[1] = __float_as_uint(vsm[(kk * 8 + qc + 4) * VSP + vf * 8 + qr]);
                mma8(co[vf], a, bb);
            }
        }
        __syncthreads();
    }

    float iA = 1.0f / lA, iB = 1.0f / lB;
    float* Zg = g_Z + ((size_t)(b * Ls + q0 + m0)) * (Hh * Dv) + h * Dv;
#pragma unroll
    for (int vf = 0; vf < 8; vf++) {
        int col = vf * 8 + 2 * qc;
        *(float2*)(Zg + (size_t)qr * (Hh * Dv) + col)       = make_float2(co[vf][0] * iA, co[vf][1] * iA);
        *(float2*)(Zg + (size_t)(qr + 8) * (Hh * Dv) + col) = make_float2(co[vf][2] * iB, co[vf][3] * iB);
    }
}

// ---------------------------------------------------------------------------
// Kernel 3: output projection, static smem + register prefetch like qkv.
// out[m][n] = sum_k Z[m][k]*Wo[n][k] + bo[n], M=4096 N=1024 K=1024.
// ---------------------------------------------------------------------------
__global__ __launch_bounds__(256) void oproj_kernel(
    const float* __restrict__ Wo, const float* __restrict__ bo,
    float* __restrict__ out)
{
    __shared__ float sa[128][SAP];
    __shared__ float swo[64][SAP];
    const int N = Dm, K = Hh * Dv;

    const float* A = g_Z + (size_t)blockIdx.x * 128 * K;
    int n0g = blockIdx.y * 64;

    int tid = threadIdx.x, lane = tid & 31, warp = tid >> 5;
    int qr = lane >> 2, qc = lane & 3;
    int m0 = (warp & 3) * 32, n0 = (warp >> 2) * 32;

    float4 ra[4], rb[2];
#pragma unroll
    for (int i = 0; i < 4; i++) {
        int id = tid + 256 * i; int r = id >> 3, c4 = id & 7;
        ra[i] = *(const float4*)(A + (size_t)r * K + c4 * 4);
    }
#pragma unroll
    for (int i = 0; i < 2; i++) {
        int id = tid + 256 * i; int r = id >> 3, c4 = id & 7;
        rb[i] = *(const float4*)(Wo + (size_t)(n0g + r) * K + c4 * 4);
    }

    float c[2][4][4] = {};

    for (int kt = 0; kt < K / 32; ++kt) {
#pragma unroll
        for (int i = 0; i < 4; i++) {
            int id = tid + 256 * i; int r = id >> 3, c4 = id & 7;
            float4 w; w.x=f2tff(ra[i].x); w.y=f2tff(ra[i].y); w.z=f2tff(ra[i].z); w.w=f2tff(ra[i].w);
            *(float4*)&sa[r][c4 * 4] = w;
        }
#pragma unroll
        for (int i = 0; i < 2; i++) {
            int id = tid + 256 * i; int r = id >> 3, c4 = id & 7;
            float4 w; w.x=f2tff(rb[i].x); w.y=f2tff(rb[i].y); w.z=f2tff(rb[i].z); w.w=f2tff(rb[i].w);
            *(float4*)&swo[r][c4 * 4] = w;
        }
        __syncthreads();
        if (kt + 1 < K / 32) {
#pragma unroll
            for (int i = 0; i < 4; i++) {
                int id = tid + 256 * i; int r = id >> 3, c4 = id & 7;
                ra[i] = *(const float4*)(A + (size_t)r * K + (kt + 1) * 32 + c4 * 4);
            }
#pragma unroll
            for (int i = 0; i < 2; i++) {
                int id = tid + 256 * i; int r = id >> 3, c4 = id & 7;
                rb[i] = *(const float4*)(Wo + (size_t)(n0g + r) * K + (kt + 1) * 32 + c4 * 4);
            }
        }
#pragma unroll
        for (int ks = 0; ks < 4; ++ks) {
            unsigned a[2][4];
#pragma unroll
            for (int mi = 0; mi < 2; mi++) {
                a[mi][0] = __float_as_uint(sa[m0 + mi * 16 + qr    ][ks * 8 + qc    ]);
                a[mi][1] = __float_as_uint(sa[m0 + mi * 16 + qr + 8][ks * 8 + qc    ]);
                a[mi][2] = __float_as_uint(sa[m0 + mi * 16 + qr    ][ks * 8 + qc + 4]);
                a[mi][3] = __float_as_uint(sa[m0 + mi * 16 + qr + 8][ks * 8 + qc + 4]);
            }
#pragma unroll
            for (int nf = 0; nf < 4; nf++) {
                unsigned bb[2];
                bb[0] = __float_as_uint(swo[n0 + nf * 8 + qr][ks * 8 + qc    ]);
                bb[1] = __float_as_uint(swo[n0 + nf * 8 + qr][ks * 8 + qc + 4]);
                mma8(c[0][nf], a[0], bb);
                mma8(c[1][nf], a[1], bb);
            }
        }
        __syncthreads();
    }

#pragma unroll
    for (int mi = 0; mi < 2; mi++) {
#pragma unroll
        for (int nf = 0; nf < 4; nf++) {
            int col = n0g + n0 + nf * 8 + 2 * qc;
            float bx = bo[col], by = bo[col + 1];
            int row = blockIdx.x * 128 + m0 + mi * 16 + qr;
            *(float2*)(out + (size_t)row * N + col)       = make_float2(c[mi][nf][0] + bx, c[mi][nf][1] + by);
            *(float2*)(out + (size_t)(row + 8) * N + col) = make_float2(c[mi][nf][2] + bx, c[mi][nf][3] + by);
        }
    }
}

// ---------------------------------------------------------------------------
extern "C" void kernel_launch(void* const* d_in, const int* in_sizes, int n_in,
                              void* d_out, int out_size)
{
    const float* X  = (const float*)d_in[0];
    const float* Wq = (const float*)d_in[1];
    const float* bq = (const float*)d_in[2];
    const float* Wk = (const float*)d_in[3];
    const float* bk = (const float*)d_in[4];
    const float* Wv = (const float*)d_in[5];
    const float* bv = (const float*)d_in[6];
    const float* Wo = (const float*)d_in[7];
    const float* bo = (const float*)d_in[8];
    float* out = (float*)d_out;

    (void)in_sizes; (void)n_in; (void)out_size;

    cudaFuncSetAttribute(flash_kernel, cudaFuncAttributeMaxDynamicSharedMemorySize, FLASH_SMEM);

    qkv_kernel<<<dim3(Ls / 128, 3 * BHN), 256>>>(X, Wq, bq, Wk, bk, Wv, bv);
    flash_kernel<<<dim3(Ls / 128, BHN), 256, FLASH_SMEM>>>();
    oproj_kernel<<<dim3((Bb * Ls) / 128, Dm / 64), 256>>>(Wo, bo, out);
}

// round 6
// speedup vs baseline: 2.1118x; 1.5099x over previous
#include <cuda_runtime.h>
#include <cuda_fp16.h>

#define Bb 2
#define Ls 2048
#define Dm 1024
#define Hh 16
#define Dk 64
#define Dv 64
#define BHN (Bb*Hh)

// fp16 scratch (halves HBM traffic of intermediates)
__device__ __half g_Q[(size_t)Bb*Hh*Ls*Dk];
__device__ __half g_K[(size_t)Bb*Hh*Ls*Dk];
__device__ __half g_V[(size_t)Bb*Hh*Ls*Dv];
__device__ __half g_Z[(size_t)Bb*Ls*Hh*Dv];   // (B, L, H*Dv) head-concat

// ---- helpers --------------------------------------------------------------
__device__ __forceinline__ unsigned packh2(float lo, float hi){
    __half2 h = __floats2half2_rn(lo, hi);
    return *(unsigned*)&h;
}
__device__ __forceinline__ void mma16(float c[4], const unsigned a[4], const unsigned b[2]){
    asm volatile("mma.sync.aligned.m16n8k16.row.col.f32.f16.f16.f32 "
        "{%0,%1,%2,%3},{%4,%5,%6,%7},{%8,%9},{%0,%1,%2,%3};"
        : "+f"(c[0]),"+f"(c[1]),"+f"(c[2]),"+f"(c[3])
        : "r"(a[0]),"r"(a[1]),"r"(a[2]),"r"(a[3]),"r"(b[0]),"r"(b[1]));
}

// ---------------------------------------------------------------------------
// Kernel 1: QKV projections (fp32 in -> fp16 out). CTA 128m x 64n, BK=32.
// 8 warps each 32x32 via m16n8k16. W tile staged as paired half2[k/2][n].
// Register prefetch between barriers (round-5 winning structure).
// ---------------------------------------------------------------------------
#define SAPH 40              // half pitch for A tiles (32 data + 8 pad)
#define SBP2 72              // half2 pitch for paired B tile (64 data + 8 pad)

__global__ __launch_bounds__(256) void qkv_kernel(
    const float* __restrict__ X,
    const float* __restrict__ Wq, const float* __restrict__ bq,
    const float* __restrict__ Wk, const float* __restrict__ bk,
    const float* __restrict__ Wv, const float* __restrict__ bv)
{
    __shared__ __half  sa[128 * SAPH];          // X tile  [m][k]
    __shared__ __half2 sbp[16 * SBP2];          // W tile  [k/2][n] paired

    int z   = blockIdx.y;
    int sel = z / BHN;
    int bh  = z - sel * BHN;
    int b   = bh / Hh;
    int h   = bh - b * Hh;

    const float* W; const float* bias; __half* out; float osc;
    if (sel == 0)      { W = Wq; bias = bq; out = g_Q; osc = 0.125f; }
    else if (sel == 1) { W = Wk; bias = bk; out = g_K; osc = 1.0f; }
    else               { W = Wv; bias = bv; out = g_V; osc = 1.0f; }
    W    += (size_t)h * Dm * Dk;
    bias += h * Dk;
    out  += (size_t)bh * Ls * Dk + (size_t)blockIdx.x * 128 * Dk;
    const float* A = X + (size_t)b * Ls * Dm + (size_t)blockIdx.x * 128 * Dm;

    int tid = threadIdx.x, lane = tid & 31, warp = tid >> 5;
    int qr = lane >> 2, qc = lane & 3;
    int m0 = (warp & 3) * 32, n0 = (warp >> 2) * 32;

    // thread slots: A: 4 iters r=id>>3, c4=id&7 ; B: kp=tid>>4 (0..15), c4b=tid&15
    int kp = tid >> 4, c4b = tid & 15;

    float4 ra[4], rb0, rb1;
#pragma unroll
    for (int i = 0; i < 4; i++) {
        int id = tid + 256 * i; int r = id >> 3, c4 = id & 7;
        ra[i] = *(const float4*)(A + (size_t)r * Dm + c4 * 4);
    }
    rb0 = *(const float4*)(W + (size_t)(2 * kp)     * Dk + c4b * 4);
    rb1 = *(const float4*)(W + (size_t)(2 * kp + 1) * Dk + c4b * 4);

    float c[2][4][4] = {};

    for (int kt = 0; kt < 32; ++kt) {
        // commit staged regs to smem (fp16 rne)
#pragma unroll
        for (int i = 0; i < 4; i++) {
            int id = tid + 256 * i; int r = id >> 3, c4 = id & 7;
            unsigned lo = packh2(ra[i].x, ra[i].y);
            unsigned hi = packh2(ra[i].z, ra[i].w);
            *(uint2*)&sa[r * SAPH + c4 * 4] = make_uint2(lo, hi);
        }
        {
            uint4 wv;
            wv.x = packh2(rb0.x, rb1.x); wv.y = packh2(rb0.y, rb1.y);
            wv.z = packh2(rb0.z, rb1.z); wv.w = packh2(rb0.w, rb1.w);
            *(uint4*)&sbp[kp * SBP2 + c4b * 4] = wv;
        }
        __syncthreads();
        if (kt + 1 < 32) {
#pragma unroll
            for (int i = 0; i < 4; i++) {
                int id = tid + 256 * i; int r = id >> 3, c4 = id & 7;
                ra[i] = *(const float4*)(A + (size_t)r * Dm + (kt + 1) * 32 + c4 * 4);
            }
            rb0 = *(const float4*)(W + (size_t)((kt + 1) * 32 + 2 * kp)     * Dk + c4b * 4);
            rb1 = *(const float4*)(W + (size_t)((kt + 1) * 32 + 2 * kp + 1) * Dk + c4b * 4);
        }
#pragma unroll
        for (int ks = 0; ks < 2; ++ks) {
            unsigned a[2][4];
#pragma unroll
            for (int mi = 0; mi < 2; mi++) {
                const __half* base0 = &sa[(m0 + mi * 16 + qr    ) * SAPH + ks * 16 + 2 * qc];
                const __half* base1 = &sa[(m0 + mi * 16 + qr + 8) * SAPH + ks * 16 + 2 * qc];
                a[mi][0] = *(const unsigned*)(base0);
                a[mi][1] = *(const unsigned*)(base1);
                a[mi][2] = *(const unsigned*)(base0 + 8);
                a[mi][3] = *(const unsigned*)(base1 + 8);
            }
#pragma unroll
            for (int nf = 0; nf < 4; nf++) {
                int col = n0 + nf * 8 + qr;
                unsigned bb[2];
                bb[0] = *(const unsigned*)&sbp[(ks * 8 + qc    ) * SBP2 + col];
                bb[1] = *(const unsigned*)&sbp[(ks * 8 + 4 + qc) * SBP2 + col];
                mma16(c[0][nf], a[0], bb);
                mma16(c[1][nf], a[1], bb);
            }
        }
        __syncthreads();
    }

#pragma unroll
    for (int mi = 0; mi < 2; mi++) {
#pragma unroll
        for (int nf = 0; nf < 4; nf++) {
            int col = n0 + nf * 8 + 2 * qc;
            float bx = bias[col], by = bias[col + 1];
            int row = m0 + mi * 16 + qr;
            *(unsigned*)(out + (size_t)row * Dk + col) =
                packh2((c[mi][nf][0] + bx) * osc, (c[mi][nf][1] + by) * osc);
            *(unsigned*)(out + (size_t)(row + 8) * Dk + col) =
                packh2((c[mi][nf][2] + bx) * osc, (c[mi][nf][3] + by) * osc);
        }
    }
}

// ---------------------------------------------------------------------------
// Kernel 2: flash attention, fp16 datapath. CTA = 128 q-rows, KV tiles of 128.
// 8 warps x (16 q-rows x 128 keys). S/P in regs; P->A frag is a pure register
// repack (fp16 C layout == A layout k-pairs). V staged paired [seq/2][dv].
// ---------------------------------------------------------------------------
#define QKP 72               // half pitch for Q/K tiles (64 data + 8 pad)
#define VP2 72               // half2 pitch for paired V tile (64 data + 8 pad)
#define FLASH_SMEM ((2 * 128 * QKP) * (int)sizeof(__half) + (64 * VP2) * (int)sizeof(__half2))

__global__ __launch_bounds__(256) void flash_kernel()
{
    extern __shared__ char smraw[];
    __half*  qs   = (__half*)smraw;                       // [128][QKP]
    __half*  ksm  = qs + 128 * QKP;                       // [128][QKP]
    __half2* vsmp = (__half2*)(ksm + 128 * QKP);          // [64][VP2] pairs along seq

    int bh = blockIdx.y;
    int q0 = blockIdx.x * 128;
    const __half* Qg = g_Q + (size_t)bh * Ls * Dk + (size_t)q0 * Dk;
    const __half* Kg = g_K + (size_t)bh * Ls * Dk;
    const __half* Vg = g_V + (size_t)bh * Ls * Dv;
    int b = bh >> 4, h = bh & 15;

    int tid = threadIdx.x, lane = tid & 31, warp = tid >> 5;
    int qr = lane >> 2, qc = lane & 3;
    int m0 = warp * 16;

    // Q tile: straight 16B copies (scale already folded in producer)
#pragma unroll
    for (int i = 0; i < 4; i++) {
        int id = tid + 256 * i; int r = id >> 3, c8 = id & 7;
        *(uint4*)&qs[r * QKP + c8 * 8] = *(const uint4*)(Qg + (size_t)r * Dk + c8 * 8);
    }

    float co[8][4] = {};
    float mA = -1e30f, mB = -1e30f, lA = 0.f, lB = 0.f;

    for (int t = 0; t < Ls / 128; ++t) {
        // K tile copy
#pragma unroll
        for (int i = 0; i < 4; i++) {
            int id = tid + 256 * i; int r = id >> 3, c8 = id & 7;
            *(uint4*)&ksm[r * QKP + c8 * 8] =
                *(const uint4*)(Kg + (size_t)(t * 128 + r) * Dk + c8 * 8);
        }
        // V tile: load two seq rows, interleave into seq-pairs
#pragma unroll
        for (int i = 0; i < 2; i++) {
            int id = tid + 256 * i; int sp = id >> 3, c8 = id & 7;
            uint4 v0 = *(const uint4*)(Vg + (size_t)(t * 128 + 2 * sp    ) * Dv + c8 * 8);
            uint4 v1 = *(const uint4*)(Vg + (size_t)(t * 128 + 2 * sp + 1) * Dv + c8 * 8);
            uint4 o0, o1;
            o0.x = __byte_perm(v0.x, v1.x, 0x5410); o0.y = __byte_perm(v0.x, v1.x, 0x7632);
            o0.z = __byte_perm(v0.y, v1.y, 0x5410); o0.w = __byte_perm(v0.y, v1.y, 0x7632);
            o1.x = __byte_perm(v0.z, v1.z, 0x5410); o1.y = __byte_perm(v0.z, v1.z, 0x7632);
            o1.z = __byte_perm(v0.w, v1.w, 0x5410); o1.w = __byte_perm(v0.w, v1.w, 0x7632);
            *(uint4*)&vsmp[sp * VP2 + c8 * 8    ] = o0;
            *(uint4*)&vsmp[sp * VP2 + c8 * 8 + 4] = o1;
        }
        __syncthreads();

        // ---- S = Q K^T : per warp 16 x 128 in registers ----
        float sc[16][4] = {};
#pragma unroll
        for (int ks = 0; ks < 4; ++ks) {
            unsigned a[4];
            const __half* b0p = &qs[(m0 + qr    ) * QKP + ks * 16 + 2 * qc];
            const __half* b1p = &qs[(m0 + qr + 8) * QKP + ks * 16 + 2 * qc];
            a[0] = *(const unsigned*)(b0p);
            a[1] = *(const unsigned*)(b1p);
            a[2] = *(const unsigned*)(b0p + 8);
            a[3] = *(const unsigned*)(b1p + 8);
#pragma unroll
            for (int nf = 0; nf < 16; nf++) {
                const __half* kp0 = &ksm[(nf * 8 + qr) * QKP + ks * 16 + 2 * qc];
                unsigned bb[2];
                bb[0] = *(const unsigned*)(kp0);
                bb[1] = *(const unsigned*)(kp0 + 8);
                mma16(sc[nf], a, bb);
            }
        }

        // ---- online softmax in registers ----
        float mxA = -1e30f, mxB = -1e30f;
#pragma unroll
        for (int nf = 0; nf < 16; nf++) {
            mxA = fmaxf(mxA, fmaxf(sc[nf][0], sc[nf][1]));
            mxB = fmaxf(mxB, fmaxf(sc[nf][2], sc[nf][3]));
        }
        mxA = fmaxf(mxA, __shfl_xor_sync(0xffffffffu, mxA, 1));
        mxA = fmaxf(mxA, __shfl_xor_sync(0xffffffffu, mxA, 2));
        mxB = fmaxf(mxB, __shfl_xor_sync(0xffffffffu, mxB, 1));
        mxB = fmaxf(mxB, __shfl_xor_sync(0xffffffffu, mxB, 2));

        float mnA = fmaxf(mA, mxA), mnB = fmaxf(mB, mxB);
        float aAl = __expf(mA - mnA), aBl = __expf(mB - mnB);
        float sA = 0.f, sB = 0.f;
#pragma unroll
        for (int nf = 0; nf < 16; nf++) {
            float p0 = __expf(sc[nf][0] - mnA);
            float p1 = __expf(sc[nf][1] - mnA);
            float p2 = __expf(sc[nf][2] - mnB);
            float p3 = __expf(sc[nf][3] - mnB);
            sA += p0 + p1; sB += p2 + p3;
            sc[nf][0] = p0; sc[nf][1] = p1; sc[nf][2] = p2; sc[nf][3] = p3;
        }
        sA += __shfl_xor_sync(0xffffffffu, sA, 1);
        sA += __shfl_xor_sync(0xffffffffu, sA, 2);
        sB += __shfl_xor_sync(0xffffffffu, sB, 1);
        sB += __shfl_xor_sync(0xffffffffu, sB, 2);
        lA = lA * aAl + sA; mA = mnA;
        lB = lB * aBl + sB; mB = mnB;

#pragma unroll
        for (int vf = 0; vf < 8; vf++) {
            co[vf][0] *= aAl; co[vf][1] *= aAl;
            co[vf][2] *= aBl; co[vf][3] *= aBl;
        }

        // ---- O += P V : P packs directly into A fragments ----
#pragma unroll
        for (int kk = 0; kk < 8; ++kk) {
            unsigned a[4];
            a[0] = packh2(sc[2*kk    ][0], sc[2*kk    ][1]);
            a[1] = packh2(sc[2*kk    ][2], sc[2*kk    ][3]);
            a[2] = packh2(sc[2*kk + 1][0], sc[2*kk + 1][1]);
            a[3] = packh2(sc[2*kk + 1][2], sc[2*kk + 1][3]);
#pragma unroll
            for (int vf = 0; vf < 8; vf++) {
                int col = vf * 8 + qr;
                unsigned bb[2];
                bb[0] = *(const unsigned*)&vsmp[(kk * 8 + qc    ) * VP2 + col];
                bb[1] = *(const unsigned*)&vsmp[(kk * 8 + 4 + qc) * VP2 + col];
                mma16(co[vf], a, bb);
            }
        }
        __syncthreads();
    }

    float iA = 1.0f / lA, iB = 1.0f / lB;
    __half* Zg = g_Z + ((size_t)(b * Ls + q0 + m0)) * (Hh * Dv) + h * Dv;
#pragma unroll
    for (int vf = 0; vf < 8; vf++) {
        int col = vf * 8 + 2 * qc;
        *(unsigned*)(Zg + (size_t)qr * (Hh * Dv) + col)       = packh2(co[vf][0] * iA, co[vf][1] * iA);
        *(unsigned*)(Zg + (size_t)(qr + 8) * (Hh * Dv) + col) = packh2(co[vf][2] * iB, co[vf][3] * iB);
    }
}

// ---------------------------------------------------------------------------
// Kernel 3: output projection (fp16 Z x fp32 Wo -> fp32 out).
// CTA 128m x 64n, BK=32; Wo is [n][k] row-major so B frags are natural half2.
// ---------------------------------------------------------------------------
__global__ __launch_bounds__(256) void oproj_kernel(
    const float* __restrict__ Wo, const float* __restrict__ bo,
    float* __restrict__ out)
{
    __shared__ __half sa[128 * SAPH];
    __shared__ __half swo[64 * SAPH];
    const int N = Dm, K = Hh * Dv;

    const __half* A = g_Z + (size_t)blockIdx.x * 128 * K;
    int n0g = blockIdx.y * 64;

    int tid = threadIdx.x, lane = tid & 31, warp = tid >> 5;
    int qr = lane >> 2, qc = lane & 3;
    int m0 = (warp & 3) * 32, n0 = (warp >> 2) * 32;

    uint4 ra[2]; float4 rb[2];
#pragma unroll
    for (int i = 0; i < 2; i++) {
        int id = tid + 256 * i; int r = id >> 2, c8 = id & 3;
        ra[i] = *(const uint4*)(A + (size_t)r * K + c8 * 8);
    }
#pragma unroll
    for (int i = 0; i < 2; i++) {
        int id = tid + 256 * i; int r = id >> 3, c4 = id & 7;
        rb[i] = *(const float4*)(Wo + (size_t)(n0g + r) * K + c4 * 4);
    }

    float c[2][4][4] = {};

    for (int kt = 0; kt < K / 32; ++kt) {
#pragma unroll
        for (int i = 0; i < 2; i++) {
            int id = tid + 256 * i; int r = id >> 2, c8 = id & 3;
            *(uint4*)&sa[r * SAPH + c8 * 8] = ra[i];
        }
#pragma unroll
        for (int i = 0; i < 2; i++) {
            int id = tid + 256 * i; int r = id >> 3, c4 = id & 7;
            unsigned lo = packh2(rb[i].x, rb[i].y);
            unsigned hi = packh2(rb[i].z, rb[i].w);
            *(uint2*)&swo[r * SAPH + c4 * 4] = make_uint2(lo, hi);
        }
        __syncthreads();
        if (kt + 1 < K / 32) {
#pragma unroll
            for (int i = 0; i < 2; i++) {
                int id = tid + 256 * i; int r = id >> 2, c8 = id & 3;
                ra[i] = *(const uint4*)(A + (size_t)r * K + (kt + 1) * 32 + c8 * 8);
            }
#pragma unroll
            for (int i = 0; i < 2; i++) {
                int id = tid + 256 * i; int r = id >> 3, c4 = id & 7;
                rb[i] = *(const float4*)(Wo + (size_t)(n0g + r) * K + (kt + 1) * 32 + c4 * 4);
            }
        }
#pragma unroll
        for (int ks = 0; ks < 2; ++ks) {
            unsigned a[2][4];
#pragma unroll
            for (int mi = 0; mi < 2; mi++) {
                const __half* b0p = &sa[(m0 + mi * 16 + qr    ) * SAPH + ks * 16 + 2 * qc];
                const __half* b1p = &sa[(m0 + mi * 16 + qr + 8) * SAPH + ks * 16 + 2 * qc];
                a[mi][0] = *(const unsigned*)(b0p);
                a[mi][1] = *(const unsigned*)(b1p);
                a[mi][2] = *(const unsigned*)(b0p + 8);
                a[mi][3] = *(const unsigned*)(b1p + 8);
            }
#pragma unroll
            for (int nf = 0; nf < 4; nf++) {
                const __half* wp = &swo[(n0 + nf * 8 + qr) * SAPH + ks * 16 + 2 * qc];
                unsigned bb[2];
                bb[0] = *(const unsigned*)(wp);
                bb[1] = *(const unsigned*)(wp + 8);
                mma16(c[0][nf], a[0], bb);
                mma16(c[1][nf], a[1], bb);
            }
        }
        __syncthreads();
    }

#pragma unroll
    for (int mi = 0; mi < 2; mi++) {
#pragma unroll
        for (int nf = 0; nf < 4; nf++) {
            int col = n0g + n0 + nf * 8 + 2 * qc;
            float bx = bo[col], by = bo[col + 1];
            int row = blockIdx.x * 128 + m0 + mi * 16 + qr;
            *(float2*)(out + (size_t)row * N + col)       = make_float2(c[mi][nf][0] + bx, c[mi][nf][1] + by);
            *(float2*)(out + (size_t)(row + 8) * N + col) = make_float2(c[mi][nf][2] + bx, c[mi][nf][3] + by);
        }
    }
}

// ---------------------------------------------------------------------------
extern "C" void kernel_launch(void* const* d_in, const int* in_sizes, int n_in,
                              void* d_out, int out_size)
{
    const float* X  = (const float*)d_in[0];
    const float* Wq = (const float*)d_in[1];
    const float* bq = (const float*)d_in[2];
    const float* Wk = (const float*)d_in[3];
    const float* bk = (const float*)d_in[4];
    const float* Wv = (const float*)d_in[5];
    const float* bv = (const float*)d_in[6];
    const float* Wo = (const float*)d_in[7];
    const float* bo = (const float*)d_in[8];
    float* out = (float*)d_out;

    (void)in_sizes; (void)n_in; (void)out_size;

    cudaFuncSetAttribute(flash_kernel, cudaFuncAttributeMaxDynamicSharedMemorySize, FLASH_SMEM);

    qkv_kernel<<<dim3(Ls / 128, 3 * BHN), 256>>>(X, Wq, bq, Wk, bk, Wv, bv);
    flash_kernel<<<dim3(Ls / 128, BHN), 256, FLASH_SMEM>>>();
    oproj_kernel<<<dim3((Bb * Ls) / 128, Dm / 64), 256>>>(Wo, bo, out);
}